// round 4
// baseline (speedup 1.0000x reference)
#include <cuda_runtime.h>
#include <cstdint>
#include <cstddef>

// ---------------- problem constants ----------------
#define BATCH    4
#define TLEN     2048
#define BT_TOTAL 8192      // BATCH*TLEN
#define DM       512       // D_MODEL
#define DI       1024      // D_INNER
#define DST      16        // D_STATE
#define NH       16        // NHEADS
#define HD       64        // HEADDIM
#define CDIM     1056      // CONV_DIM
#define DPROJ    2096      // D_IN_PROJ
#define DINT     256       // D_INTER
#define NLAYERS  4
#define EPSV     1e-5f

// scan chunking
#define CL   64
#define NC   (TLEN / CL)         // 32 chunks
#define NBH  64                  // BATCH * NH

// ---------------- device scratch (no runtime alloc allowed) ----------------
__device__ float g_res[BT_TOTAL * DM];
__device__ float g_h  [BT_TOTAL * DM];
__device__ float g_x  [BT_TOTAL * DM];
__device__ float g_hh [BT_TOTAL * DM];
__device__ float g_zx [BT_TOTAL * DPROJ];
__device__ float g_xc [BT_TOTAL * DI];
__device__ float g_y  [BT_TOTAL * DI];
__device__ float g_g  [BT_TOTAL * DINT];
__device__ float g_Bc [BT_TOTAL * DST];
__device__ float g_Cc [BT_TOTAL * DST];
__device__ float g_dt [BT_TOTAL * NH];
__device__ float g_dA [BT_TOTAL * NH];
__device__ float g_P  [NBH * TLEN];
__device__ float g_S  [NC * NBH * HD * DST];

__device__ __forceinline__ float siluf(float v) {
    return v / (1.f + __expf(-v));
}

__device__ __forceinline__ uint32_t f2tf32(float x) {
    uint32_t u;
    asm("cvt.rna.tf32.f32 %0, %1;" : "=r"(u) : "f"(x));
    return u;
}

__device__ __forceinline__ void cp_async16(uint32_t saddr, const void* gptr, bool pred) {
    int sz = pred ? 16 : 0;
    asm volatile("cp.async.cg.shared.global [%0], [%1], 16, %2;\n"
                 :: "r"(saddr), "l"(gptr), "r"(sz));
}

// ---------------- fused (optional add) + LayerNorm, row = 512 ----------------
__global__ void addln_kernel(const float* __restrict__ a,
                             const float* __restrict__ bsrc,
                             const float* __restrict__ w,
                             const float* __restrict__ bias,
                             float* __restrict__ resOut,
                             float* __restrict__ hOut)
{
    int row = blockIdx.x;
    int tid = threadIdx.x;                 // 128 threads, 4 floats each
    const float4* a4 = (const float4*)(a + (size_t)row * DM);
    float4 v = a4[tid];
    if (bsrc) {
        float4 r = ((const float4*)(bsrc + (size_t)row * DM))[tid];
        v.x += r.x; v.y += r.y; v.z += r.z; v.w += r.w;
    }
    if (resOut) ((float4*)(resOut + (size_t)row * DM))[tid] = v;

    float s  = v.x + v.y + v.z + v.w;
    float ss = v.x*v.x + v.y*v.y + v.z*v.z + v.w*v.w;
    #pragma unroll
    for (int o = 16; o; o >>= 1) {
        s  += __shfl_xor_sync(0xffffffffu, s,  o);
        ss += __shfl_xor_sync(0xffffffffu, ss, o);
    }
    __shared__ float shs[4], shss[4];
    int wid = tid >> 5;
    if ((tid & 31) == 0) { shs[wid] = s; shss[wid] = ss; }
    __syncthreads();
    s  = shs[0]  + shs[1]  + shs[2]  + shs[3];
    ss = shss[0] + shss[1] + shss[2] + shss[3];
    float mu  = s * (1.f / DM);
    float var = ss * (1.f / DM) - mu * mu;
    float inv = rsqrtf(var + EPSV);

    float4 wv = ((const float4*)w)[tid];
    float4 bv = ((const float4*)bias)[tid];
    float4 o;
    o.x = (v.x - mu) * inv * wv.x + bv.x;
    o.y = (v.y - mu) * inv * wv.y + bv.y;
    o.z = (v.z - mu) * inv * wv.z + bv.z;
    o.w = (v.w - mu) * inv * wv.w + bv.w;
    ((float4*)(hOut + (size_t)row * DM))[tid] = o;
}

// ---------------- tf32 tensor-core GEMM with cp.async 3-stage pipeline ----------------
// C[M,N] = A[M,K]*W[N,K]^T (+Cadd). Block tile 128x128, K-tile 16, 256 threads.
// Raw fp32 staged in smem via cp.async; cvt.rna.tf32 applied at fragment load
// (same rounding as R3 -> identical numerics).
#define TBM 128
#define TBN 128
#define TBK 16
#define SPAD 20                         // smem row stride (floats): conflict-free
#define ASZ  (TBM * SPAD)               // floats per A stage
#define STGF (2 * ASZ)                  // floats per stage (A + B)
#define NSTG 3
#define GEMM_SMEM (NSTG * STGF * 4)     // 61440 bytes

__global__ __launch_bounds__(256)
void tgemm_kernel(const float* __restrict__ A, const float* __restrict__ W,
                  const float* __restrict__ Cadd, float* __restrict__ C,
                  int M, int N, int K)
{
    extern __shared__ float smem[];
    uint32_t sbase = (uint32_t)__cvta_generic_to_shared(smem);

    int tid = threadIdx.x;
    int wid = tid >> 5;
    int lane = tid & 31;
    int g = lane >> 2;          // 0..7
    int t = lane & 3;           // 0..3
    int warp_m = wid >> 2;      // 0..1
    int warp_n = wid & 3;       // 0..3

    int bm = blockIdx.y * TBM;
    int bn = blockIdx.x * TBN;

    int r0 = tid >> 2;          // 0..63
    int q0 = tid & 3;           // k-quad

    float acc[4][4][4];
    #pragma unroll
    for (int i = 0; i < 4; i++)
        #pragma unroll
        for (int j = 0; j < 4; j++)
            #pragma unroll
            for (int d = 0; d < 4; d++) acc[i][j][d] = 0.f;

    int KT = K / TBK;

    // stage loader: 8 cp.async (2 A quads + 2 B quads per thread? -> 2 each)
    auto load_stage = [&](int stage, int kt) {
        int kbase = kt * TBK;
        uint32_t as = sbase + (uint32_t)(stage * STGF) * 4;
        uint32_t bs = as + (uint32_t)ASZ * 4;
        #pragma unroll
        for (int it = 0; it < 2; it++) {
            int r = r0 + it * 64;
            cp_async16(as + (uint32_t)(r * SPAD + q0 * 4) * 4,
                       A + (size_t)(bm + r) * K + kbase + q0 * 4, true);
            int n = bn + r;
            cp_async16(bs + (uint32_t)(r * SPAD + q0 * 4) * 4,
                       W + (size_t)n * K + kbase + q0 * 4, n < N);
        }
        asm volatile("cp.async.commit_group;");
    };

    // prologue: fill NSTG-1 stages (all our KT >= 16)
    load_stage(0, 0);
    load_stage(1, 1);

    for (int kt = 0; kt < KT; kt++) {
        int stage = kt % NSTG;
        asm volatile("cp.async.wait_group %0;" :: "n"(NSTG - 2));
        __syncthreads();

        // issue next stage load (into the slot computed last iteration)
        if (kt + 2 < KT) load_stage((kt + 2) % NSTG, kt + 2);

        const float* As = smem + stage * STGF;
        const float* Bs = As + ASZ;

        #pragma unroll
        for (int ks = 0; ks < 2; ks++) {
            int kb = ks * 8;
            uint32_t af[4][4];
            uint32_t bf[4][2];
            #pragma unroll
            for (int mf = 0; mf < 4; mf++) {
                int mrow = warp_m * 64 + mf * 16 + g;
                af[mf][0] = f2tf32(As[(mrow    ) * SPAD + kb + t]);
                af[mf][1] = f2tf32(As[(mrow + 8) * SPAD + kb + t]);
                af[mf][2] = f2tf32(As[(mrow    ) * SPAD + kb + t + 4]);
                af[mf][3] = f2tf32(As[(mrow + 8) * SPAD + kb + t + 4]);
            }
            #pragma unroll
            for (int nf = 0; nf < 4; nf++) {
                int nrow = warp_n * 32 + nf * 8 + g;
                bf[nf][0] = f2tf32(Bs[nrow * SPAD + kb + t]);
                bf[nf][1] = f2tf32(Bs[nrow * SPAD + kb + t + 4]);
            }
            #pragma unroll
            for (int mf = 0; mf < 4; mf++)
                #pragma unroll
                for (int nf = 0; nf < 4; nf++) {
                    asm volatile(
                        "mma.sync.aligned.m16n8k8.row.col.f32.tf32.tf32.f32 "
                        "{%0,%1,%2,%3}, {%4,%5,%6,%7}, {%8,%9}, {%0,%1,%2,%3};"
                        : "+f"(acc[mf][nf][0]), "+f"(acc[mf][nf][1]),
                          "+f"(acc[mf][nf][2]), "+f"(acc[mf][nf][3])
                        : "r"(af[mf][0]), "r"(af[mf][1]),
                          "r"(af[mf][2]), "r"(af[mf][3]),
                          "r"(bf[nf][0]), "r"(bf[nf][1]));
                }
        }
        __syncthreads();
    }

    // ---- epilogue ----
    #pragma unroll
    for (int mf = 0; mf < 4; mf++) {
        int row0 = bm + warp_m * 64 + mf * 16 + g;
        #pragma unroll
        for (int nf = 0; nf < 4; nf++) {
            int col = bn + warp_n * 32 + nf * 8 + 2 * t;
            if (col < N) {
                float2 v0 = make_float2(acc[mf][nf][0], acc[mf][nf][1]);
                float2 v1 = make_float2(acc[mf][nf][2], acc[mf][nf][3]);
                if (Cadd) {
                    float2 o0 = *(const float2*)(Cadd + (size_t)row0 * N + col);
                    float2 o1 = *(const float2*)(Cadd + (size_t)(row0 + 8) * N + col);
                    v0.x += o0.x; v0.y += o0.y;
                    v1.x += o1.x; v1.y += o1.y;
                }
                *(float2*)(C + (size_t)row0 * N + col) = v0;
                *(float2*)(C + (size_t)(row0 + 8) * N + col) = v1;
            }
        }
    }
}

// ---------------- depthwise conv (dir-dep) + silu + dt/dA ----------------
__global__ void convdt_kernel(const float* __restrict__ zx,
                              const float* __restrict__ cw,
                              const float* __restrict__ cb,
                              const float* __restrict__ dtb,
                              const float* __restrict__ alog,
                              int backward,
                              float* __restrict__ xc, float* __restrict__ Bo,
                              float* __restrict__ Co, float* __restrict__ dto,
                              float* __restrict__ dAo)
{
    int row = blockIdx.x;
    int b = row >> 11;
    int t = row & (TLEN - 1);
    for (int w = threadIdx.x; w < CDIM + NH; w += blockDim.x) {
        if (w < CDIM) {
            int ch = w;
            float acc = cb[ch];
            #pragma unroll
            for (int k = 0; k < 4; k++) {
                int tt = backward ? (t + 3 - k) : (t - 3 + k);
                if (tt >= 0 && tt < TLEN)
                    acc = fmaf(zx[(size_t)(b * TLEN + tt) * DPROJ + DI + ch],
                               cw[ch * 4 + k], acc);
            }
            float s = siluf(acc);
            if (ch < DI)            xc[(size_t)row * DI + ch] = s;
            else if (ch < DI + DST) Bo[row * DST + (ch - DI)] = s;
            else                    Co[row * DST + (ch - DI - DST)] = s;
        } else {
            int hd = w - CDIM;
            float raw = zx[(size_t)row * DPROJ + (DI + CDIM) + hd] + dtb[hd];
            float dtv = (raw > 20.f) ? raw : log1pf(__expf(raw));
            float Ah  = -__expf(alog[hd]);
            dto[row * NH + hd] = dtv;
            dAo[row * NH + hd] = __expf(dtv * Ah);
        }
    }
}

// ---------------- chunk-parallel selective scan ----------------
#define SCH 64
__global__ void scan1_kernel(const float* __restrict__ xc, const float* __restrict__ Bg,
                             const float* __restrict__ Cg, const float* __restrict__ dtg,
                             const float* __restrict__ dAg, const float* __restrict__ Dp,
                             float* __restrict__ y, float* __restrict__ Pbuf,
                             float* __restrict__ Sbuf, int backward)
{
    __shared__ float4 sB[SCH][4];
    __shared__ float4 sC[SCH][4];
    __shared__ float  sdt[SCH], sdA[SCH];
    __shared__ float  sx[SCH][HD];

    int bh = blockIdx.x / NC;
    int c  = blockIdx.x % NC;
    int b = bh >> 4;
    int h = bh & 15;
    int p = threadIdx.x;                   // 0..63

    float hs[16];
    #pragma unroll
    for (int n = 0; n < 16; n++) hs[n] = 0.f;
    float Dh = Dp[h];
    float Pv = 1.f;

    int sBase = c * CL;
    for (int c0 = sBase; c0 < sBase + CL; c0 += SCH) {
        __syncthreads();
        #pragma unroll
        for (int it = 0; it < 4; it++) {
            int f = p + it * 64;           // 0..255
            int s = f >> 2, q = f & 3;
            int t = backward ? (TLEN - 1 - (c0 + s)) : (c0 + s);
            int bt = b * TLEN + t;
            sB[s][q] = *(const float4*)(Bg + (size_t)bt * DST + q * 4);
            sC[s][q] = *(const float4*)(Cg + (size_t)bt * DST + q * 4);
        }
        {
            int s = p;
            int t = backward ? (TLEN - 1 - (c0 + s)) : (c0 + s);
            int bt = b * TLEN + t;
            sdt[s] = dtg[bt * NH + h];
            sdA[s] = dAg[bt * NH + h];
        }
        #pragma unroll 4
        for (int s = 0; s < SCH; s++) {
            int t = backward ? (TLEN - 1 - (c0 + s)) : (c0 + s);
            sx[s][p] = xc[(size_t)(b * TLEN + t) * DI + h * HD + p];
        }
        __syncthreads();

        #pragma unroll 2
        for (int s = 0; s < SCH; s++) {
            float xv  = sx[s][p];
            float dAv = sdA[s];
            float u   = sdt[s] * xv;
            Pv *= dAv;
            float4 B0 = sB[s][0], B1 = sB[s][1], B2 = sB[s][2], B3 = sB[s][3];
            float4 C0 = sC[s][0], C1 = sC[s][1], C2 = sC[s][2], C3 = sC[s][3];
            float a0, a1, a2, a3;
            hs[0]  = fmaf(hs[0],  dAv, u * B0.x); a0 = hs[0]  * C0.x;
            hs[1]  = fmaf(hs[1],  dAv, u * B0.y); a1 = hs[1]  * C0.y;
            hs[2]  = fmaf(hs[2],  dAv, u * B0.z); a2 = hs[2]  * C0.z;
            hs[3]  = fmaf(hs[3],  dAv, u * B0.w); a3 = hs[3]  * C0.w;
            hs[4]  = fmaf(hs[4],  dAv, u * B1.x); a0 = fmaf(hs[4],  C1.x, a0);
            hs[5]  = fmaf(hs[5],  dAv, u * B1.y); a1 = fmaf(hs[5],  C1.y, a1);
            hs[6]  = fmaf(hs[6],  dAv, u * B1.z); a2 = fmaf(hs[6],  C1.z, a2);
            hs[7]  = fmaf(hs[7],  dAv, u * B1.w); a3 = fmaf(hs[7],  C1.w, a3);
            hs[8]  = fmaf(hs[8],  dAv, u * B2.x); a0 = fmaf(hs[8],  C2.x, a0);
            hs[9]  = fmaf(hs[9],  dAv, u * B2.y); a1 = fmaf(hs[9],  C2.y, a1);
            hs[10] = fmaf(hs[10], dAv, u * B2.z); a2 = fmaf(hs[10], C2.z, a2);
            hs[11] = fmaf(hs[11], dAv, u * B2.w); a3 = fmaf(hs[11], C2.w, a3);
            hs[12] = fmaf(hs[12], dAv, u * B3.x); a0 = fmaf(hs[12], C3.x, a0);
            hs[13] = fmaf(hs[13], dAv, u * B3.y); a1 = fmaf(hs[13], C3.y, a1);
            hs[14] = fmaf(hs[14], dAv, u * B3.z); a2 = fmaf(hs[14], C3.z, a2);
            hs[15] = fmaf(hs[15], dAv, u * B3.w); a3 = fmaf(hs[15], C3.w, a3);
            float acc = fmaf(Dh, xv, (a0 + a1) + (a2 + a3));
            int t = backward ? (TLEN - 1 - (c0 + s)) : (c0 + s);
            y[(size_t)(b * TLEN + t) * DI + h * HD + p] = acc;
            if (p == 0) Pbuf[bh * TLEN + c0 + s] = Pv;
        }
    }
    float* sp = Sbuf + (size_t)(((c * NBH + bh) * HD + p) * DST);
    #pragma unroll
    for (int q = 0; q < 4; q++)
        ((float4*)sp)[q] = make_float4(hs[q*4+0], hs[q*4+1], hs[q*4+2], hs[q*4+3]);
}

__global__ void scan2_kernel(float* __restrict__ Sbuf, const float* __restrict__ Pbuf)
{
    int idx = blockIdx.x * blockDim.x + threadIdx.x;   // (bh, p)
    int bh = idx >> 6;
    int p  = idx & 63;
    float hin[16];
    #pragma unroll
    for (int n = 0; n < 16; n++) hin[n] = 0.f;
    for (int c = 0; c < NC; c++) {
        float Pe = Pbuf[bh * TLEN + (c + 1) * CL - 1];
        float* sp = Sbuf + (size_t)(((c * NBH + bh) * HD + p) * DST);
        float S[16];
        #pragma unroll
        for (int q = 0; q < 4; q++) {
            float4 v = ((const float4*)sp)[q];
            S[q*4+0] = v.x; S[q*4+1] = v.y; S[q*4+2] = v.z; S[q*4+3] = v.w;
        }
        #pragma unroll
        for (int q = 0; q < 4; q++)
            ((float4*)sp)[q] = make_float4(hin[q*4+0], hin[q*4+1], hin[q*4+2], hin[q*4+3]);
        #pragma unroll
        for (int n = 0; n < 16; n++) hin[n] = fmaf(Pe, hin[n], S[n]);
    }
}

__global__ void scan3_kernel(const float* __restrict__ Cg, const float* __restrict__ Pbuf,
                             const float* __restrict__ Sbuf, float* __restrict__ y,
                             int backward)
{
    __shared__ float4 sC[SCH][4];
    __shared__ float  sP[SCH];

    int bh = blockIdx.x / (NC - 1);
    int c  = blockIdx.x % (NC - 1) + 1;
    int b = bh >> 4;
    int h = bh & 15;
    int p = threadIdx.x;

    float hin[16];
    {
        const float* sp = Sbuf + (size_t)(((c * NBH + bh) * HD + p) * DST);
        #pragma unroll
        for (int q = 0; q < 4; q++) {
            float4 v = ((const float4*)sp)[q];
            hin[q*4+0] = v.x; hin[q*4+1] = v.y; hin[q*4+2] = v.z; hin[q*4+3] = v.w;
        }
    }

    int sBase = c * CL;
    for (int c0 = sBase; c0 < sBase + CL; c0 += SCH) {
        __syncthreads();
        #pragma unroll
        for (int it = 0; it < 4; it++) {
            int f = p + it * 64;
            int s = f >> 2, q = f & 3;
            int t = backward ? (TLEN - 1 - (c0 + s)) : (c0 + s);
            int bt = b * TLEN + t;
            sC[s][q] = *(const float4*)(Cg + (size_t)bt * DST + q * 4);
        }
        sP[p] = Pbuf[bh * TLEN + c0 + p];
        __syncthreads();

        #pragma unroll 4
        for (int s = 0; s < SCH; s++) {
            float4 C0 = sC[s][0], C1 = sC[s][1], C2 = sC[s][2], C3 = sC[s][3];
            float a0 = hin[0] * C0.x;
            float a1 = hin[1] * C0.y;
            float a2 = hin[2] * C0.z;
            float a3 = hin[3] * C0.w;
            a0 = fmaf(hin[4],  C1.x, a0); a1 = fmaf(hin[5],  C1.y, a1);
            a2 = fmaf(hin[6],  C1.z, a2); a3 = fmaf(hin[7],  C1.w, a3);
            a0 = fmaf(hin[8],  C2.x, a0); a1 = fmaf(hin[9],  C2.y, a1);
            a2 = fmaf(hin[10], C2.z, a2); a3 = fmaf(hin[11], C2.w, a3);
            a0 = fmaf(hin[12], C3.x, a0); a1 = fmaf(hin[13], C3.y, a1);
            a2 = fmaf(hin[14], C3.z, a2); a3 = fmaf(hin[15], C3.w, a3);
            float dot = (a0 + a1) + (a2 + a3);
            int t = backward ? (TLEN - 1 - (c0 + s)) : (c0 + s);
            size_t yi = (size_t)(b * TLEN + t) * DI + h * HD + p;
            y[yi] = fmaf(sP[s], dot, y[yi]);
        }
    }
}

// ---------------- gate with silu(z) + RMSNorm * gw ----------------
__global__ void gatenorm_kernel(float* __restrict__ y, const float* __restrict__ zx,
                                const float* __restrict__ gw)
{
    int row = blockIdx.x;
    int tid = threadIdx.x;                 // 256 threads, float4 each
    float4 v = ((const float4*)(y + (size_t)row * DI))[tid];
    float4 z = ((const float4*)(zx + (size_t)row * DPROJ))[tid];
    v.x *= siluf(z.x); v.y *= siluf(z.y); v.z *= siluf(z.z); v.w *= siluf(z.w);
    float ss = v.x*v.x + v.y*v.y + v.z*v.z + v.w*v.w;
    #pragma unroll
    for (int o = 16; o; o >>= 1) ss += __shfl_xor_sync(0xffffffffu, ss, o);
    __shared__ float sh[8];
    int wid = tid >> 5;
    if ((tid & 31) == 0) sh[wid] = ss;
    __syncthreads();
    ss = sh[0] + sh[1] + sh[2] + sh[3] + sh[4] + sh[5] + sh[6] + sh[7];
    float scale = rsqrtf(ss * (1.f / DI) + EPSV);
    float4 g = ((const float4*)gw)[tid];
    v.x *= scale * g.x; v.y *= scale * g.y; v.z *= scale * g.z; v.w *= scale * g.w;
    ((float4*)(y + (size_t)row * DI))[tid] = v;
}

// ---------------- GLU: g = hh[:, :256] * silu(hh[:, 256:]) ----------------
__global__ void glu_kernel(const float* __restrict__ hh, float* __restrict__ g)
{
    int idx = blockIdx.x * blockDim.x + threadIdx.x;
    if (idx >= BT_TOTAL * DINT) return;
    int row = idx >> 8;
    int c   = idx & 255;
    float a  = hh[(size_t)row * DM + c];
    float gg = hh[(size_t)row * DM + DINT + c];
    g[idx] = a * siluf(gg);
}

// ---------------- host orchestration ----------------
static inline void launch_gemm(const float* A, const float* W, const float* Cadd,
                               float* C, int M, int N, int K)
{
    dim3 grid((N + TBN - 1) / TBN, (M + TBM - 1) / TBM);
    tgemm_kernel<<<grid, 256, GEMM_SMEM>>>(A, W, Cadd, C, M, N, K);
}

extern "C" void kernel_launch(void* const* d_in, const int* in_sizes, int n_in,
                              void* d_out, int out_size)
{
    static bool attr_set = false;
    if (!attr_set) {
        cudaFuncSetAttribute(tgemm_kernel,
                             cudaFuncAttributeMaxDynamicSharedMemorySize, GEMM_SMEM);
        attr_set = true;
    }

    const float* x_in = (const float*)d_in[0];
    const float* n1w  = (const float*)d_in[1];
    const float* n1b  = (const float*)d_in[2];
    const float* inw  = (const float*)d_in[3];
    const float* cw   = (const float*)d_in[4];
    const float* cb   = (const float*)d_in[5];
    const float* dtb  = (const float*)d_in[6];
    const float* alog = (const float*)d_in[7];
    const float* Dp   = (const float*)d_in[8];
    const float* gw   = (const float*)d_in[9];
    const float* ow   = (const float*)d_in[10];
    const float* n2w  = (const float*)d_in[11];
    const float* n2b  = (const float*)d_in[12];
    const float* f1w  = (const float*)d_in[13];
    const float* f2w  = (const float*)d_in[14];
    const float* nfw  = (const float*)d_in[15];
    const float* nfb  = (const float*)d_in[16];
    float* out = (float*)d_out;

    float *p_res, *p_h, *p_x, *p_hh, *p_zx, *p_xc, *p_y, *p_g, *p_B, *p_C, *p_dt, *p_dA;
    float *p_P, *p_S;
    cudaGetSymbolAddress((void**)&p_res, g_res);
    cudaGetSymbolAddress((void**)&p_h,   g_h);
    cudaGetSymbolAddress((void**)&p_x,   g_x);
    cudaGetSymbolAddress((void**)&p_hh,  g_hh);
    cudaGetSymbolAddress((void**)&p_zx,  g_zx);
    cudaGetSymbolAddress((void**)&p_xc,  g_xc);
    cudaGetSymbolAddress((void**)&p_y,   g_y);
    cudaGetSymbolAddress((void**)&p_g,   g_g);
    cudaGetSymbolAddress((void**)&p_B,   g_Bc);
    cudaGetSymbolAddress((void**)&p_C,   g_Cc);
    cudaGetSymbolAddress((void**)&p_dt,  g_dt);
    cudaGetSymbolAddress((void**)&p_dA,  g_dA);
    cudaGetSymbolAddress((void**)&p_P,   g_P);
    cudaGetSymbolAddress((void**)&p_S,   g_S);

    for (int l = 0; l < NLAYERS; l++) {
        int back = l & 1;
        const float* xin = (l == 0) ? x_in : p_x;

        addln_kernel<<<BT_TOTAL, 128>>>(xin, (l == 0) ? nullptr : p_res,
                                        n1w + l * DM, n1b + l * DM, p_res, p_h);
        launch_gemm(p_h, inw + (size_t)l * DPROJ * DM, nullptr, p_zx,
                    BT_TOTAL, DPROJ, DM);
        convdt_kernel<<<BT_TOTAL, 256>>>(p_zx, cw + l * CDIM * 4, cb + l * CDIM,
                                         dtb + l * NH, alog + l * NH, back,
                                         p_xc, p_B, p_C, p_dt, p_dA);
        scan1_kernel<<<NBH * NC, 64>>>(p_xc, p_B, p_C, p_dt, p_dA, Dp + l * NH,
                                       p_y, p_P, p_S, back);
        scan2_kernel<<<16, 256>>>(p_S, p_P);
        scan3_kernel<<<NBH * (NC - 1), 64>>>(p_C, p_P, p_S, p_y, back);

        gatenorm_kernel<<<BT_TOTAL, 256>>>(p_y, p_zx, gw + l * DI);
        launch_gemm(p_y, ow + (size_t)l * DM * DI, p_res, p_res, BT_TOTAL, DM, DI);
        addln_kernel<<<BT_TOTAL, 128>>>(p_res, nullptr, n2w + l * DM, n2b + l * DM,
                                        nullptr, p_h);
        launch_gemm(p_h, f1w + (size_t)l * 2 * DINT * DM, nullptr, p_hh,
                    BT_TOTAL, 2 * DINT, DM);
        glu_kernel<<<(BT_TOTAL * DINT + 255) / 256, 256>>>(p_hh, p_g);
        launch_gemm(p_g, f2w + (size_t)l * DM * DINT, nullptr, p_x,
                    BT_TOTAL, DM, DINT);
    }
    addln_kernel<<<BT_TOTAL, 128>>>(p_x, p_res, nfw, nfb, nullptr, out);
}

// round 5
// speedup vs baseline: 1.0307x; 1.0307x over previous
#include <cuda_runtime.h>
#include <cuda_fp16.h>
#include <cstdint>
#include <cstddef>

// ---------------- problem constants ----------------
#define BATCH    4
#define TLEN     2048
#define BT_TOTAL 8192      // BATCH*TLEN
#define DM       512       // D_MODEL
#define DI       1024      // D_INNER
#define DST      16        // D_STATE
#define NH       16        // NHEADS
#define HD       64        // HEADDIM
#define CDIM     1056      // CONV_DIM
#define DPROJ    2096      // D_IN_PROJ
#define DINT     256       // D_INTER
#define NLAYERS  4
#define EPSV     1e-5f

// scan chunking
#define CL   64
#define NC   (TLEN / CL)         // 32 chunks
#define NBH  64                  // BATCH * NH

// ---------------- device scratch (no runtime alloc allowed) ----------------
__device__ float g_res[BT_TOTAL * DM];
__device__ float g_h  [BT_TOTAL * DM];
__device__ float g_x  [BT_TOTAL * DM];
__device__ float g_hh [BT_TOTAL * DM];
__device__ float g_zx [BT_TOTAL * DPROJ];
__device__ float g_xc [BT_TOTAL * DI];
__device__ float g_y  [BT_TOTAL * DI];
__device__ float g_g  [BT_TOTAL * DINT];
__device__ float g_Bc [BT_TOTAL * DST];
__device__ float g_Cc [BT_TOTAL * DST];
__device__ float g_dt [BT_TOTAL * NH];
__device__ float g_dA [BT_TOTAL * NH];
__device__ float g_P  [NBH * TLEN];
__device__ float g_S  [NC * NBH * HD * DST];

__device__ __forceinline__ float siluf(float v) {
    return v / (1.f + __expf(-v));
}

__device__ __forceinline__ uint32_t pack_f16x2(float lo, float hi) {
    uint32_t u;
    asm("cvt.rn.f16x2.f32 %0, %1, %2;" : "=r"(u) : "f"(hi), "f"(lo));
    return u;
}

__device__ __forceinline__ void cp_async16(uint32_t saddr, const void* gptr, bool pred) {
    int sz = pred ? 16 : 0;
    asm volatile("cp.async.cg.shared.global [%0], [%1], 16, %2;\n"
                 :: "r"(saddr), "l"(gptr), "r"(sz));
}

// ---------------- fused (optional add) + LayerNorm, row = 512 ----------------
__global__ void addln_kernel(const float* __restrict__ a,
                             const float* __restrict__ bsrc,
                             const float* __restrict__ w,
                             const float* __restrict__ bias,
                             float* __restrict__ resOut,
                             float* __restrict__ hOut)
{
    int row = blockIdx.x;
    int tid = threadIdx.x;                 // 128 threads, 4 floats each
    const float4* a4 = (const float4*)(a + (size_t)row * DM);
    float4 v = a4[tid];
    if (bsrc) {
        float4 r = ((const float4*)(bsrc + (size_t)row * DM))[tid];
        v.x += r.x; v.y += r.y; v.z += r.z; v.w += r.w;
    }
    if (resOut) ((float4*)(resOut + (size_t)row * DM))[tid] = v;

    float s  = v.x + v.y + v.z + v.w;
    float ss = v.x*v.x + v.y*v.y + v.z*v.z + v.w*v.w;
    #pragma unroll
    for (int o = 16; o; o >>= 1) {
        s  += __shfl_xor_sync(0xffffffffu, s,  o);
        ss += __shfl_xor_sync(0xffffffffu, ss, o);
    }
    __shared__ float shs[4], shss[4];
    int wid = tid >> 5;
    if ((tid & 31) == 0) { shs[wid] = s; shss[wid] = ss; }
    __syncthreads();
    s  = shs[0]  + shs[1]  + shs[2]  + shs[3];
    ss = shss[0] + shss[1] + shss[2] + shss[3];
    float mu  = s * (1.f / DM);
    float var = ss * (1.f / DM) - mu * mu;
    float inv = rsqrtf(var + EPSV);

    float4 wv = ((const float4*)w)[tid];
    float4 bv = ((const float4*)bias)[tid];
    float4 o;
    o.x = (v.x - mu) * inv * wv.x + bv.x;
    o.y = (v.y - mu) * inv * wv.y + bv.y;
    o.z = (v.z - mu) * inv * wv.z + bv.z;
    o.w = (v.w - mu) * inv * wv.w + bv.w;
    ((float4*)(hOut + (size_t)row * DM))[tid] = o;
}

// ---------------- f16 tensor-core GEMM (fp32 accum) with cp.async pipeline ----------------
// C[M,N] = A[M,K]*W[N,K]^T (+Cadd). Block tile 128x128, K-tile 16, 256 threads.
// fp32 staged in smem via cp.async; cvt.rn.f16x2 at fragment load; mma m16n8k16.
#define TBM 128
#define TBN 128
#define TBK 16
#define SPAD 20                         // smem row stride (floats): conflict-free
#define ASZ  (TBM * SPAD)               // floats per A stage
#define STGF (2 * ASZ)                  // floats per stage (A + B)
#define NSTG 3
#define GEMM_SMEM (NSTG * STGF * 4)     // 61440 bytes

__global__ __launch_bounds__(256)
void tgemm_kernel(const float* __restrict__ A, const float* __restrict__ W,
                  const float* __restrict__ Cadd, float* __restrict__ C,
                  int M, int N, int K)
{
    extern __shared__ float smem[];
    uint32_t sbase = (uint32_t)__cvta_generic_to_shared(smem);

    int tid = threadIdx.x;
    int wid = tid >> 5;
    int lane = tid & 31;
    int g = lane >> 2;          // 0..7
    int t = lane & 3;           // 0..3
    int warp_m = wid >> 2;      // 0..1
    int warp_n = wid & 3;       // 0..3

    int bm = blockIdx.y * TBM;
    int bn = blockIdx.x * TBN;

    int r0 = tid >> 2;          // 0..63
    int q0 = tid & 3;           // k-quad

    float acc[4][4][4];
    #pragma unroll
    for (int i = 0; i < 4; i++)
        #pragma unroll
        for (int j = 0; j < 4; j++)
            #pragma unroll
            for (int d = 0; d < 4; d++) acc[i][j][d] = 0.f;

    int KT = K / TBK;

    auto load_stage = [&](int stage, int kt) {
        int kbase = kt * TBK;
        uint32_t as = sbase + (uint32_t)(stage * STGF) * 4;
        uint32_t bs = as + (uint32_t)ASZ * 4;
        #pragma unroll
        for (int it = 0; it < 2; it++) {
            int r = r0 + it * 64;
            cp_async16(as + (uint32_t)(r * SPAD + q0 * 4) * 4,
                       A + (size_t)(bm + r) * K + kbase + q0 * 4, true);
            int n = bn + r;
            cp_async16(bs + (uint32_t)(r * SPAD + q0 * 4) * 4,
                       W + (size_t)n * K + kbase + q0 * 4, n < N);
        }
        asm volatile("cp.async.commit_group;");
    };

    load_stage(0, 0);
    load_stage(1, 1);

    for (int kt = 0; kt < KT; kt++) {
        int stage = kt % NSTG;
        asm volatile("cp.async.wait_group %0;" :: "n"(NSTG - 2));
        __syncthreads();

        if (kt + 2 < KT) load_stage((kt + 2) % NSTG, kt + 2);

        const float* As = smem + stage * STGF;
        const float* Bs = As + ASZ;

        // one m16n8k16 step consumes the whole 16-wide k-tile
        uint32_t af[4][4];      // [mf][reg], f16x2 each
        uint32_t bf[4][2];      // [nf][reg]
        #pragma unroll
        for (int mf = 0; mf < 4; mf++) {
            int mrow = warp_m * 64 + mf * 16 + g;
            float2 p0 = *(const float2*)(&As[(mrow    ) * SPAD + 2 * t]);
            float2 p1 = *(const float2*)(&As[(mrow + 8) * SPAD + 2 * t]);
            float2 p2 = *(const float2*)(&As[(mrow    ) * SPAD + 2 * t + 8]);
            float2 p3 = *(const float2*)(&As[(mrow + 8) * SPAD + 2 * t + 8]);
            af[mf][0] = pack_f16x2(p0.x, p0.y);
            af[mf][1] = pack_f16x2(p1.x, p1.y);
            af[mf][2] = pack_f16x2(p2.x, p2.y);
            af[mf][3] = pack_f16x2(p3.x, p3.y);
        }
        #pragma unroll
        for (int nf = 0; nf < 4; nf++) {
            int nrow = warp_n * 32 + nf * 8 + g;
            float2 p0 = *(const float2*)(&Bs[nrow * SPAD + 2 * t]);
            float2 p1 = *(const float2*)(&Bs[nrow * SPAD + 2 * t + 8]);
            bf[nf][0] = pack_f16x2(p0.x, p0.y);
            bf[nf][1] = pack_f16x2(p1.x, p1.y);
        }
        #pragma unroll
        for (int mf = 0; mf < 4; mf++)
            #pragma unroll
            for (int nf = 0; nf < 4; nf++) {
                asm volatile(
                    "mma.sync.aligned.m16n8k16.row.col.f32.f16.f16.f32 "
                    "{%0,%1,%2,%3}, {%4,%5,%6,%7}, {%8,%9}, {%0,%1,%2,%3};"
                    : "+f"(acc[mf][nf][0]), "+f"(acc[mf][nf][1]),
                      "+f"(acc[mf][nf][2]), "+f"(acc[mf][nf][3])
                    : "r"(af[mf][0]), "r"(af[mf][1]),
                      "r"(af[mf][2]), "r"(af[mf][3]),
                      "r"(bf[nf][0]), "r"(bf[nf][1]));
            }
        __syncthreads();
    }

    // ---- epilogue ----
    #pragma unroll
    for (int mf = 0; mf < 4; mf++) {
        int row0 = bm + warp_m * 64 + mf * 16 + g;
        #pragma unroll
        for (int nf = 0; nf < 4; nf++) {
            int col = bn + warp_n * 32 + nf * 8 + 2 * t;
            if (col < N) {
                float2 v0 = make_float2(acc[mf][nf][0], acc[mf][nf][1]);
                float2 v1 = make_float2(acc[mf][nf][2], acc[mf][nf][3]);
                if (Cadd) {
                    float2 o0 = *(const float2*)(Cadd + (size_t)row0 * N + col);
                    float2 o1 = *(const float2*)(Cadd + (size_t)(row0 + 8) * N + col);
                    v0.x += o0.x; v0.y += o0.y;
                    v1.x += o1.x; v1.y += o1.y;
                }
                *(float2*)(C + (size_t)row0 * N + col) = v0;
                *(float2*)(C + (size_t)(row0 + 8) * N + col) = v1;
            }
        }
    }
}

// ---------------- depthwise conv (dir-dep) + silu + dt/dA ----------------
__global__ void convdt_kernel(const float* __restrict__ zx,
                              const float* __restrict__ cw,
                              const float* __restrict__ cb,
                              const float* __restrict__ dtb,
                              const float* __restrict__ alog,
                              int backward,
                              float* __restrict__ xc, float* __restrict__ Bo,
                              float* __restrict__ Co, float* __restrict__ dto,
                              float* __restrict__ dAo)
{
    int row = blockIdx.x;
    int b = row >> 11;
    int t = row & (TLEN - 1);
    for (int w = threadIdx.x; w < CDIM + NH; w += blockDim.x) {
        if (w < CDIM) {
            int ch = w;
            float acc = cb[ch];
            #pragma unroll
            for (int k = 0; k < 4; k++) {
                int tt = backward ? (t + 3 - k) : (t - 3 + k);
                if (tt >= 0 && tt < TLEN)
                    acc = fmaf(zx[(size_t)(b * TLEN + tt) * DPROJ + DI + ch],
                               cw[ch * 4 + k], acc);
            }
            float s = siluf(acc);
            if (ch < DI)            xc[(size_t)row * DI + ch] = s;
            else if (ch < DI + DST) Bo[row * DST + (ch - DI)] = s;
            else                    Co[row * DST + (ch - DI - DST)] = s;
        } else {
            int hd = w - CDIM;
            float raw = zx[(size_t)row * DPROJ + (DI + CDIM) + hd] + dtb[hd];
            float dtv = (raw > 20.f) ? raw : log1pf(__expf(raw));
            float Ah  = -__expf(alog[hd]);
            dto[row * NH + hd] = dtv;
            dAo[row * NH + hd] = __expf(dtv * Ah);
        }
    }
}

// ---------------- chunk-parallel selective scan ----------------
#define SCH 64
__global__ void scan1_kernel(const float* __restrict__ xc, const float* __restrict__ Bg,
                             const float* __restrict__ Cg, const float* __restrict__ dtg,
                             const float* __restrict__ dAg, const float* __restrict__ Dp,
                             float* __restrict__ y, float* __restrict__ Pbuf,
                             float* __restrict__ Sbuf, int backward)
{
    __shared__ float4 sB[SCH][4];
    __shared__ float4 sC[SCH][4];
    __shared__ float  sdt[SCH], sdA[SCH];
    __shared__ float  sx[SCH][HD];

    int bh = blockIdx.x / NC;
    int c  = blockIdx.x % NC;
    int b = bh >> 4;
    int h = bh & 15;
    int p = threadIdx.x;                   // 0..63

    float hs[16];
    #pragma unroll
    for (int n = 0; n < 16; n++) hs[n] = 0.f;
    float Dh = Dp[h];
    float Pv = 1.f;

    int sBase = c * CL;
    for (int c0 = sBase; c0 < sBase + CL; c0 += SCH) {
        __syncthreads();
        #pragma unroll
        for (int it = 0; it < 4; it++) {
            int f = p + it * 64;           // 0..255
            int s = f >> 2, q = f & 3;
            int t = backward ? (TLEN - 1 - (c0 + s)) : (c0 + s);
            int bt = b * TLEN + t;
            sB[s][q] = *(const float4*)(Bg + (size_t)bt * DST + q * 4);
            sC[s][q] = *(const float4*)(Cg + (size_t)bt * DST + q * 4);
        }
        {
            int s = p;
            int t = backward ? (TLEN - 1 - (c0 + s)) : (c0 + s);
            int bt = b * TLEN + t;
            sdt[s] = dtg[bt * NH + h];
            sdA[s] = dAg[bt * NH + h];
        }
        #pragma unroll 4
        for (int s = 0; s < SCH; s++) {
            int t = backward ? (TLEN - 1 - (c0 + s)) : (c0 + s);
            sx[s][p] = xc[(size_t)(b * TLEN + t) * DI + h * HD + p];
        }
        __syncthreads();

        #pragma unroll 2
        for (int s = 0; s < SCH; s++) {
            float xv  = sx[s][p];
            float dAv = sdA[s];
            float u   = sdt[s] * xv;
            Pv *= dAv;
            float4 B0 = sB[s][0], B1 = sB[s][1], B2 = sB[s][2], B3 = sB[s][3];
            float4 C0 = sC[s][0], C1 = sC[s][1], C2 = sC[s][2], C3 = sC[s][3];
            float a0, a1, a2, a3;
            hs[0]  = fmaf(hs[0],  dAv, u * B0.x); a0 = hs[0]  * C0.x;
            hs[1]  = fmaf(hs[1],  dAv, u * B0.y); a1 = hs[1]  * C0.y;
            hs[2]  = fmaf(hs[2],  dAv, u * B0.z); a2 = hs[2]  * C0.z;
            hs[3]  = fmaf(hs[3],  dAv, u * B0.w); a3 = hs[3]  * C0.w;
            hs[4]  = fmaf(hs[4],  dAv, u * B1.x); a0 = fmaf(hs[4],  C1.x, a0);
            hs[5]  = fmaf(hs[5],  dAv, u * B1.y); a1 = fmaf(hs[5],  C1.y, a1);
            hs[6]  = fmaf(hs[6],  dAv, u * B1.z); a2 = fmaf(hs[6],  C1.z, a2);
            hs[7]  = fmaf(hs[7],  dAv, u * B1.w); a3 = fmaf(hs[7],  C1.w, a3);
            hs[8]  = fmaf(hs[8],  dAv, u * B2.x); a0 = fmaf(hs[8],  C2.x, a0);
            hs[9]  = fmaf(hs[9],  dAv, u * B2.y); a1 = fmaf(hs[9],  C2.y, a1);
            hs[10] = fmaf(hs[10], dAv, u * B2.z); a2 = fmaf(hs[10], C2.z, a2);
            hs[11] = fmaf(hs[11], dAv, u * B2.w); a3 = fmaf(hs[11], C2.w, a3);
            hs[12] = fmaf(hs[12], dAv, u * B3.x); a0 = fmaf(hs[12], C3.x, a0);
            hs[13] = fmaf(hs[13], dAv, u * B3.y); a1 = fmaf(hs[13], C3.y, a1);
            hs[14] = fmaf(hs[14], dAv, u * B3.z); a2 = fmaf(hs[14], C3.z, a2);
            hs[15] = fmaf(hs[15], dAv, u * B3.w); a3 = fmaf(hs[15], C3.w, a3);
            float acc = fmaf(Dh, xv, (a0 + a1) + (a2 + a3));
            int t = backward ? (TLEN - 1 - (c0 + s)) : (c0 + s);
            y[(size_t)(b * TLEN + t) * DI + h * HD + p] = acc;
            if (p == 0) Pbuf[bh * TLEN + c0 + s] = Pv;
        }
    }
    float* sp = Sbuf + (size_t)(((c * NBH + bh) * HD + p) * DST);
    #pragma unroll
    for (int q = 0; q < 4; q++)
        ((float4*)sp)[q] = make_float4(hs[q*4+0], hs[q*4+1], hs[q*4+2], hs[q*4+3]);
}

__global__ void scan2_kernel(float* __restrict__ Sbuf, const float* __restrict__ Pbuf)
{
    int idx = blockIdx.x * blockDim.x + threadIdx.x;   // (bh, p)
    int bh = idx >> 6;
    int p  = idx & 63;
    float hin[16];
    #pragma unroll
    for (int n = 0; n < 16; n++) hin[n] = 0.f;
    for (int c = 0; c < NC; c++) {
        float Pe = Pbuf[bh * TLEN + (c + 1) * CL - 1];
        float* sp = Sbuf + (size_t)(((c * NBH + bh) * HD + p) * DST);
        float S[16];
        #pragma unroll
        for (int q = 0; q < 4; q++) {
            float4 v = ((const float4*)sp)[q];
            S[q*4+0] = v.x; S[q*4+1] = v.y; S[q*4+2] = v.z; S[q*4+3] = v.w;
        }
        #pragma unroll
        for (int q = 0; q < 4; q++)
            ((float4*)sp)[q] = make_float4(hin[q*4+0], hin[q*4+1], hin[q*4+2], hin[q*4+3]);
        #pragma unroll
        for (int n = 0; n < 16; n++) hin[n] = fmaf(Pe, hin[n], S[n]);
    }
}

__global__ void scan3_kernel(const float* __restrict__ Cg, const float* __restrict__ Pbuf,
                             const float* __restrict__ Sbuf, float* __restrict__ y,
                             int backward)
{
    __shared__ float4 sC[SCH][4];
    __shared__ float  sP[SCH];

    int bh = blockIdx.x / (NC - 1);
    int c  = blockIdx.x % (NC - 1) + 1;
    int b = bh >> 4;
    int h = bh & 15;
    int p = threadIdx.x;

    float hin[16];
    {
        const float* sp = Sbuf + (size_t)(((c * NBH + bh) * HD + p) * DST);
        #pragma unroll
        for (int q = 0; q < 4; q++) {
            float4 v = ((const float4*)sp)[q];
            hin[q*4+0] = v.x; hin[q*4+1] = v.y; hin[q*4+2] = v.z; hin[q*4+3] = v.w;
        }
    }

    int sBase = c * CL;
    for (int c0 = sBase; c0 < sBase + CL; c0 += SCH) {
        __syncthreads();
        #pragma unroll
        for (int it = 0; it < 4; it++) {
            int f = p + it * 64;
            int s = f >> 2, q = f & 3;
            int t = backward ? (TLEN - 1 - (c0 + s)) : (c0 + s);
            int bt = b * TLEN + t;
            sC[s][q] = *(const float4*)(Cg + (size_t)bt * DST + q * 4);
        }
        sP[p] = Pbuf[bh * TLEN + c0 + p];
        __syncthreads();

        #pragma unroll 4
        for (int s = 0; s < SCH; s++) {
            float4 C0 = sC[s][0], C1 = sC[s][1], C2 = sC[s][2], C3 = sC[s][3];
            float a0 = hin[0] * C0.x;
            float a1 = hin[1] * C0.y;
            float a2 = hin[2] * C0.z;
            float a3 = hin[3] * C0.w;
            a0 = fmaf(hin[4],  C1.x, a0); a1 = fmaf(hin[5],  C1.y, a1);
            a2 = fmaf(hin[6],  C1.z, a2); a3 = fmaf(hin[7],  C1.w, a3);
            a0 = fmaf(hin[8],  C2.x, a0); a1 = fmaf(hin[9],  C2.y, a1);
            a2 = fmaf(hin[10], C2.z, a2); a3 = fmaf(hin[11], C2.w, a3);
            a0 = fmaf(hin[12], C3.x, a0); a1 = fmaf(hin[13], C3.y, a1);
            a2 = fmaf(hin[14], C3.z, a2); a3 = fmaf(hin[15], C3.w, a3);
            float dot = (a0 + a1) + (a2 + a3);
            int t = backward ? (TLEN - 1 - (c0 + s)) : (c0 + s);
            size_t yi = (size_t)(b * TLEN + t) * DI + h * HD + p;
            y[yi] = fmaf(sP[s], dot, y[yi]);
        }
    }
}

// ---------------- gate with silu(z) + RMSNorm * gw ----------------
__global__ void gatenorm_kernel(float* __restrict__ y, const float* __restrict__ zx,
                                const float* __restrict__ gw)
{
    int row = blockIdx.x;
    int tid = threadIdx.x;                 // 256 threads, float4 each
    float4 v = ((const float4*)(y + (size_t)row * DI))[tid];
    float4 z = ((const float4*)(zx + (size_t)row * DPROJ))[tid];
    v.x *= siluf(z.x); v.y *= siluf(z.y); v.z *= siluf(z.z); v.w *= siluf(z.w);
    float ss = v.x*v.x + v.y*v.y + v.z*v.z + v.w*v.w;
    #pragma unroll
    for (int o = 16; o; o >>= 1) ss += __shfl_xor_sync(0xffffffffu, ss, o);
    __shared__ float sh[8];
    int wid = tid >> 5;
    if ((tid & 31) == 0) sh[wid] = ss;
    __syncthreads();
    ss = sh[0] + sh[1] + sh[2] + sh[3] + sh[4] + sh[5] + sh[6] + sh[7];
    float scale = rsqrtf(ss * (1.f / DI) + EPSV);
    float4 g = ((const float4*)gw)[tid];
    v.x *= scale * g.x; v.y *= scale * g.y; v.z *= scale * g.z; v.w *= scale * g.w;
    ((float4*)(y + (size_t)row * DI))[tid] = v;
}

// ---------------- GLU: g = hh[:, :256] * silu(hh[:, 256:]) ----------------
__global__ void glu_kernel(const float* __restrict__ hh, float* __restrict__ g)
{
    int idx = blockIdx.x * blockDim.x + threadIdx.x;
    if (idx >= BT_TOTAL * DINT) return;
    int row = idx >> 8;
    int c   = idx & 255;
    float a  = hh[(size_t)row * DM + c];
    float gg = hh[(size_t)row * DM + DINT + c];
    g[idx] = a * siluf(gg);
}

// ---------------- host orchestration ----------------
static inline void launch_gemm(const float* A, const float* W, const float* Cadd,
                               float* C, int M, int N, int K)
{
    dim3 grid((N + TBN - 1) / TBN, (M + TBM - 1) / TBM);
    tgemm_kernel<<<grid, 256, GEMM_SMEM>>>(A, W, Cadd, C, M, N, K);
}

extern "C" void kernel_launch(void* const* d_in, const int* in_sizes, int n_in,
                              void* d_out, int out_size)
{
    static bool attr_set = false;
    if (!attr_set) {
        cudaFuncSetAttribute(tgemm_kernel,
                             cudaFuncAttributeMaxDynamicSharedMemorySize, GEMM_SMEM);
        attr_set = true;
    }

    const float* x_in = (const float*)d_in[0];
    const float* n1w  = (const float*)d_in[1];
    const float* n1b  = (const float*)d_in[2];
    const float* inw  = (const float*)d_in[3];
    const float* cw   = (const float*)d_in[4];
    const float* cb   = (const float*)d_in[5];
    const float* dtb  = (const float*)d_in[6];
    const float* alog = (const float*)d_in[7];
    const float* Dp   = (const float*)d_in[8];
    const float* gw   = (const float*)d_in[9];
    const float* ow   = (const float*)d_in[10];
    const float* n2w  = (const float*)d_in[11];
    const float* n2b  = (const float*)d_in[12];
    const float* f1w  = (const float*)d_in[13];
    const float* f2w  = (const float*)d_in[14];
    const float* nfw  = (const float*)d_in[15];
    const float* nfb  = (const float*)d_in[16];
    float* out = (float*)d_out;

    float *p_res, *p_h, *p_x, *p_hh, *p_zx, *p_xc, *p_y, *p_g, *p_B, *p_C, *p_dt, *p_dA;
    float *p_P, *p_S;
    cudaGetSymbolAddress((void**)&p_res, g_res);
    cudaGetSymbolAddress((void**)&p_h,   g_h);
    cudaGetSymbolAddress((void**)&p_x,   g_x);
    cudaGetSymbolAddress((void**)&p_hh,  g_hh);
    cudaGetSymbolAddress((void**)&p_zx,  g_zx);
    cudaGetSymbolAddress((void**)&p_xc,  g_xc);
    cudaGetSymbolAddress((void**)&p_y,   g_y);
    cudaGetSymbolAddress((void**)&p_g,   g_g);
    cudaGetSymbolAddress((void**)&p_B,   g_Bc);
    cudaGetSymbolAddress((void**)&p_C,   g_Cc);
    cudaGetSymbolAddress((void**)&p_dt,  g_dt);
    cudaGetSymbolAddress((void**)&p_dA,  g_dA);
    cudaGetSymbolAddress((void**)&p_P,   g_P);
    cudaGetSymbolAddress((void**)&p_S,   g_S);

    for (int l = 0; l < NLAYERS; l++) {
        int back = l & 1;
        const float* xin = (l == 0) ? x_in : p_x;

        addln_kernel<<<BT_TOTAL, 128>>>(xin, (l == 0) ? nullptr : p_res,
                                        n1w + l * DM, n1b + l * DM, p_res, p_h);
        launch_gemm(p_h, inw + (size_t)l * DPROJ * DM, nullptr, p_zx,
                    BT_TOTAL, DPROJ, DM);
        convdt_kernel<<<BT_TOTAL, 256>>>(p_zx, cw + l * CDIM * 4, cb + l * CDIM,
                                         dtb + l * NH, alog + l * NH, back,
                                         p_xc, p_B, p_C, p_dt, p_dA);
        scan1_kernel<<<NBH * NC, 64>>>(p_xc, p_B, p_C, p_dt, p_dA, Dp + l * NH,
                                       p_y, p_P, p_S, back);
        scan2_kernel<<<16, 256>>>(p_S, p_P);
        scan3_kernel<<<NBH * (NC - 1), 64>>>(p_C, p_P, p_S, p_y, back);

        gatenorm_kernel<<<BT_TOTAL, 256>>>(p_y, p_zx, gw + l * DI);
        launch_gemm(p_y, ow + (size_t)l * DM * DI, p_res, p_res, BT_TOTAL, DM, DI);
        addln_kernel<<<BT_TOTAL, 128>>>(p_res, nullptr, n2w + l * DM, n2b + l * DM,
                                        nullptr, p_h);
        launch_gemm(p_h, f1w + (size_t)l * 2 * DINT * DM, nullptr, p_hh,
                    BT_TOTAL, 2 * DINT, DM);
        glu_kernel<<<(BT_TOTAL * DINT + 255) / 256, 256>>>(p_hh, p_g);
        launch_gemm(p_g, f2w + (size_t)l * DM * DINT, nullptr, p_x,
                    BT_TOTAL, DM, DINT);
    }
    addln_kernel<<<BT_TOTAL, 128>>>(p_x, p_res, nfw, nfb, nullptr, out);
}